// round 1
// baseline (speedup 1.0000x reference)
#include <cuda_runtime.h>
#include <math_constants.h>

#define BATCH   4
#define N_UP    16384
#define N_DOWN  4096
#define C_UP    384
#define C_DOWN  512
#define C_OUT   512
#define KNN     3
#define EPSW    1e-8f

// Scratch (allocation-free rule: __device__ globals)
__device__ float g_down_f[BATCH * N_DOWN * C_OUT];   // 32 MB
__device__ int   g_idx[BATCH * N_UP * KNN];
__device__ float g_w[BATCH * N_UP * KNN];

// ---------------------------------------------------------------------------
// GEMM1: g_down_f[m, o] = sum_c down_features[m, c] * W_down[o, c] + b_down[o]
// M = BATCH*N_DOWN = 16384, N = 512, K = 512
// 128x128 tile, BK=16, 256 threads, 8x8 microtile
// ---------------------------------------------------------------------------
__global__ __launch_bounds__(256) void gemm_down_kernel(
    const float* __restrict__ A,     // [M, C_DOWN]
    const float* __restrict__ W,     // [C_OUT, C_DOWN]
    const float* __restrict__ bias)  // [C_OUT]
{
    const int K = C_DOWN;
    __shared__ float As[16][128];
    __shared__ float Bs[16][128];

    const int tid = threadIdx.x;
    const int m0 = blockIdx.y * 128;
    const int n0 = blockIdx.x * 128;
    const int lr = tid >> 2;          // 0..63
    const int lk = (tid & 3) * 4;     // 0,4,8,12
    const int ty = tid >> 4;          // 0..15 -> rows ty*8..ty*8+7
    const int tx = tid & 15;          // 0..15 -> cols tx*4 and tx*4+64

    float acc[8][8];
#pragma unroll
    for (int i = 0; i < 8; i++)
#pragma unroll
        for (int j = 0; j < 8; j++) acc[i][j] = 0.0f;

    for (int kt = 0; kt < K; kt += 16) {
#pragma unroll
        for (int i = 0; i < 2; i++) {
            float4 va = *(const float4*)&A[(size_t)(m0 + lr + 64 * i) * K + kt + lk];
            As[lk + 0][lr + 64 * i] = va.x;
            As[lk + 1][lr + 64 * i] = va.y;
            As[lk + 2][lr + 64 * i] = va.z;
            As[lk + 3][lr + 64 * i] = va.w;
            float4 vw = *(const float4*)&W[(size_t)(n0 + lr + 64 * i) * K + kt + lk];
            Bs[lk + 0][lr + 64 * i] = vw.x;
            Bs[lk + 1][lr + 64 * i] = vw.y;
            Bs[lk + 2][lr + 64 * i] = vw.z;
            Bs[lk + 3][lr + 64 * i] = vw.w;
        }
        __syncthreads();
#pragma unroll
        for (int k = 0; k < 16; k++) {
            float a[8], b[8];
            *(float4*)&a[0] = *(float4*)&As[k][ty * 8];
            *(float4*)&a[4] = *(float4*)&As[k][ty * 8 + 4];
            *(float4*)&b[0] = *(float4*)&Bs[k][tx * 4];
            *(float4*)&b[4] = *(float4*)&Bs[k][tx * 4 + 64];
#pragma unroll
            for (int i = 0; i < 8; i++)
#pragma unroll
                for (int j = 0; j < 8; j++)
                    acc[i][j] = fmaf(a[i], b[j], acc[i][j]);
        }
        __syncthreads();
    }

#pragma unroll
    for (int i = 0; i < 8; i++) {
        int m = m0 + ty * 8 + i;
#pragma unroll
        for (int jg = 0; jg < 2; jg++) {
            int n = n0 + tx * 4 + jg * 64;
            float4 o;
            o.x = acc[i][jg * 4 + 0] + bias[n + 0];
            o.y = acc[i][jg * 4 + 1] + bias[n + 1];
            o.z = acc[i][jg * 4 + 2] + bias[n + 2];
            o.w = acc[i][jg * 4 + 3] + bias[n + 3];
            *(float4*)&g_down_f[(size_t)m * C_OUT + n] = o;
        }
    }
}

// ---------------------------------------------------------------------------
// KNN: per up point, find 3 nearest down points (squared distance, ref formula
// ordering: u2 + d2 - 2*dot; we rank by t = d2 - 2*dot which is ordering-
// equivalent since u2 is constant per up point). Weights = normalized 1/(d+eps).
// Stability: strict < insertion keeps earliest index on ties (matches top_k).
// ---------------------------------------------------------------------------
__global__ __launch_bounds__(256) void knn_kernel(
    const float* __restrict__ up_points,    // [BATCH, N_UP, 3]
    const float* __restrict__ down_points)  // [BATCH, N_DOWN, 3]
{
    __shared__ float4 sp[2048];   // 32 KB: (x, y, z, x^2+y^2+z^2)

    const int b = blockIdx.y;
    const int n = blockIdx.x * 256 + threadIdx.x;

    const float* up = up_points + (size_t)(b * N_UP + n) * 3;
    const float ux = up[0], uy = up[1], uz = up[2];
    const float u2 = ux * ux + uy * uy + uz * uz;
    const float a0 = -2.0f * ux, a1 = -2.0f * uy, a2 = -2.0f * uz;

    float bd0 = CUDART_INF_F, bd1 = CUDART_INF_F, bd2 = CUDART_INF_F;
    int   bi0 = 0, bi1 = 0, bi2 = 0;

    for (int phase = 0; phase < 2; phase++) {
        const int mbase = phase * 2048;
        __syncthreads();
        for (int i = threadIdx.x; i < 2048; i += 256) {
            const float* dp = down_points + (size_t)(b * N_DOWN + mbase + i) * 3;
            float x = dp[0], y = dp[1], z = dp[2];
            sp[i] = make_float4(x, y, z, x * x + y * y + z * z);
        }
        __syncthreads();

        for (int m = 0; m < 2048; m += 8) {
            float t[8];
#pragma unroll
            for (int j = 0; j < 8; j++) {
                float4 p = sp[m + j];
                t[j] = fmaf(a0, p.x, fmaf(a1, p.y, fmaf(a2, p.z, p.w)));
            }
            float mn01 = fminf(t[0], t[1]);
            float mn23 = fminf(t[2], t[3]);
            float mn45 = fminf(t[4], t[5]);
            float mn67 = fminf(t[6], t[7]);
            float mn = fminf(fminf(mn01, mn23), fminf(mn45, mn67));
            if (mn < bd2) {
#pragma unroll
                for (int j = 0; j < 8; j++) {
                    float d = t[j];
                    if (d < bd2) {
                        int mi = mbase + m + j;
                        if (d < bd1) {
                            bd2 = bd1; bi2 = bi1;
                            if (d < bd0) { bd1 = bd0; bi1 = bi0; bd0 = d; bi0 = mi; }
                            else          { bd1 = d;  bi1 = mi; }
                        } else {
                            bd2 = d; bi2 = mi;
                        }
                    }
                }
            }
        }
    }

    // Actual squared distances (reference-equivalent) and normalized weights.
    float d0 = bd0 + u2, d1 = bd1 + u2, d2 = bd2 + u2;
    float w0 = 1.0f / (d0 + EPSW);
    float w1 = 1.0f / (d1 + EPSW);
    float w2 = 1.0f / (d2 + EPSW);
    float inv = 1.0f / (w0 + w1 + w2);

    const int base = (b * N_UP + n) * KNN;
    g_idx[base + 0] = bi0; g_idx[base + 1] = bi1; g_idx[base + 2] = bi2;
    g_w[base + 0] = w0 * inv; g_w[base + 1] = w1 * inv; g_w[base + 2] = w2 * inv;
}

// ---------------------------------------------------------------------------
// Fused output GEMM + interpolation epilogue:
// out[m, o] = sum_c up_features[m, c]*W_up[o, c] + b_up[o]
//             + sum_k w[m, k] * g_down_f[b, idx[m, k], o]
// M = BATCH*N_UP = 65536, N = 512, K = 384
// ---------------------------------------------------------------------------
__global__ __launch_bounds__(256) void fused_out_kernel(
    const float* __restrict__ A,     // up_features [M, C_UP]
    const float* __restrict__ W,     // W_up [C_OUT, C_UP]
    const float* __restrict__ bias,  // b_up [C_OUT]
    float* __restrict__ out)         // [M, C_OUT]
{
    const int K = C_UP;
    __shared__ float As[16][128];
    __shared__ float Bs[16][128];

    const int tid = threadIdx.x;
    const int m0 = blockIdx.y * 128;
    const int n0 = blockIdx.x * 128;
    const int lr = tid >> 2;
    const int lk = (tid & 3) * 4;
    const int ty = tid >> 4;
    const int tx = tid & 15;

    float acc[8][8];
#pragma unroll
    for (int i = 0; i < 8; i++)
#pragma unroll
        for (int j = 0; j < 8; j++) acc[i][j] = 0.0f;

    for (int kt = 0; kt < K; kt += 16) {
#pragma unroll
        for (int i = 0; i < 2; i++) {
            float4 va = *(const float4*)&A[(size_t)(m0 + lr + 64 * i) * K + kt + lk];
            As[lk + 0][lr + 64 * i] = va.x;
            As[lk + 1][lr + 64 * i] = va.y;
            As[lk + 2][lr + 64 * i] = va.z;
            As[lk + 3][lr + 64 * i] = va.w;
            float4 vw = *(const float4*)&W[(size_t)(n0 + lr + 64 * i) * K + kt + lk];
            Bs[lk + 0][lr + 64 * i] = vw.x;
            Bs[lk + 1][lr + 64 * i] = vw.y;
            Bs[lk + 2][lr + 64 * i] = vw.z;
            Bs[lk + 3][lr + 64 * i] = vw.w;
        }
        __syncthreads();
#pragma unroll
        for (int k = 0; k < 16; k++) {
            float a[8], b[8];
            *(float4*)&a[0] = *(float4*)&As[k][ty * 8];
            *(float4*)&a[4] = *(float4*)&As[k][ty * 8 + 4];
            *(float4*)&b[0] = *(float4*)&Bs[k][tx * 4];
            *(float4*)&b[4] = *(float4*)&Bs[k][tx * 4 + 64];
#pragma unroll
            for (int i = 0; i < 8; i++)
#pragma unroll
                for (int j = 0; j < 8; j++)
                    acc[i][j] = fmaf(a[i], b[j], acc[i][j]);
        }
        __syncthreads();
    }

#pragma unroll
    for (int i = 0; i < 8; i++) {
        const int m = m0 + ty * 8 + i;
        const int bb = m >> 14;   // m / N_UP
        const float* df = g_down_f + (size_t)bb * N_DOWN * C_OUT;
        const int ib = m * KNN;
        const int i0 = g_idx[ib + 0], i1 = g_idx[ib + 1], i2 = g_idx[ib + 2];
        const float w0 = g_w[ib + 0], w1 = g_w[ib + 1], w2 = g_w[ib + 2];
#pragma unroll
        for (int jg = 0; jg < 2; jg++) {
            const int n = n0 + tx * 4 + jg * 64;
            float4 f0 = *(const float4*)&df[(size_t)i0 * C_OUT + n];
            float4 f1 = *(const float4*)&df[(size_t)i1 * C_OUT + n];
            float4 f2 = *(const float4*)&df[(size_t)i2 * C_OUT + n];
            float4 o;
            o.x = acc[i][jg * 4 + 0] + bias[n + 0] + w0 * f0.x + w1 * f1.x + w2 * f2.x;
            o.y = acc[i][jg * 4 + 1] + bias[n + 1] + w0 * f0.y + w1 * f1.y + w2 * f2.y;
            o.z = acc[i][jg * 4 + 2] + bias[n + 2] + w0 * f0.z + w1 * f1.z + w2 * f2.z;
            o.w = acc[i][jg * 4 + 3] + bias[n + 3] + w0 * f0.w + w1 * f1.w + w2 * f2.w;
            *(float4*)&out[(size_t)m * C_OUT + n] = o;
        }
    }
}

// ---------------------------------------------------------------------------
extern "C" void kernel_launch(void* const* d_in, const int* in_sizes, int n_in,
                              void* d_out, int out_size) {
    (void)in_sizes; (void)n_in; (void)out_size;
    const float* up_points     = (const float*)d_in[0];
    const float* up_features   = (const float*)d_in[1];
    const float* down_points   = (const float*)d_in[2];
    const float* down_features = (const float*)d_in[3];
    const float* W_up          = (const float*)d_in[4];
    const float* b_up          = (const float*)d_in[5];
    const float* W_down        = (const float*)d_in[6];
    const float* b_down        = (const float*)d_in[7];
    float* out = (float*)d_out;

    dim3 g1(C_OUT / 128, (BATCH * N_DOWN) / 128);   // (4, 128)
    gemm_down_kernel<<<g1, 256>>>(down_features, W_down, b_down);

    dim3 g2(N_UP / 256, BATCH);                      // (64, 4)
    knn_kernel<<<g2, 256>>>(up_points, down_points);

    dim3 g3(C_OUT / 128, (BATCH * N_UP) / 128);      // (4, 512)
    fused_out_kernel<<<g3, 256>>>(up_features, W_up, b_up, out);
}

// round 2
// speedup vs baseline: 1.0759x; 1.0759x over previous
#include <cuda_runtime.h>
#include <math_constants.h>

#define BATCH   4
#define N_UP    16384
#define N_DOWN  4096
#define C_UP    384
#define C_DOWN  512
#define C_OUT   512
#define KNN     3
#define EPSW    1e-8f

// Scratch (allocation-free rule: __device__ globals)
__device__ float g_down_f[BATCH * N_DOWN * C_OUT];   // 32 MB
__device__ int   g_idx[BATCH * N_UP * KNN];
__device__ float g_w[BATCH * N_UP * KNN];

// ---- packed f32x2 helpers (sm_103a) ---------------------------------------
__device__ __forceinline__ void ffma2(unsigned long long& d,
                                      unsigned long long a,
                                      unsigned long long b) {
    asm("fma.rn.f32x2 %0, %1, %2, %0;" : "+l"(d) : "l"(a), "l"(b));
}
__device__ __forceinline__ unsigned long long dup2(float a) {
    unsigned long long r;
    asm("mov.b64 %0, {%1, %1};" : "=l"(r) : "f"(a));
    return r;
}
union F4U {
    float4 v;
    unsigned long long u[2];
    float f[4];
};

// ---------------------------------------------------------------------------
// GEMM1: g_down_f[m, o] = sum_c down_features[m, c] * W_down[o, c] + b_down[o]
// M = 16384, N = 512, K = 512. 128x128 tile, BK=16, 256 thr, 8x8 microtile,
// double-buffered smem + packed f32x2 FMA.
// ---------------------------------------------------------------------------
__global__ __launch_bounds__(256) void gemm_down_kernel(
    const float* __restrict__ A,     // [M, C_DOWN]
    const float* __restrict__ W,     // [C_OUT, C_DOWN]
    const float* __restrict__ bias)  // [C_OUT]
{
    const int K = C_DOWN;
    __shared__ float As[2][16][128];
    __shared__ float Bs[2][16][128];

    const int tid = threadIdx.x;
    const int m0 = blockIdx.y * 128;
    const int n0 = blockIdx.x * 128;
    const int lr = tid >> 2;          // 0..63
    const int lk = (tid & 3) * 4;     // 0,4,8,12
    const int ty = tid >> 4;          // 0..15
    const int tx = tid & 15;          // 0..15

    unsigned long long acc2[8][4];
#pragma unroll
    for (int i = 0; i < 8; i++)
#pragma unroll
        for (int j = 0; j < 4; j++) acc2[i][j] = 0ull;

    const float* pa0 = &A[(size_t)(m0 + lr) * K + lk];
    const float* pa1 = &A[(size_t)(m0 + lr + 64) * K + lk];
    const float* pw0 = &W[(size_t)(n0 + lr) * K + lk];
    const float* pw1 = &W[(size_t)(n0 + lr + 64) * K + lk];

    // preload tile 0
    {
        float4 va0 = *(const float4*)pa0;
        float4 va1 = *(const float4*)pa1;
        float4 vw0 = *(const float4*)pw0;
        float4 vw1 = *(const float4*)pw1;
        As[0][lk + 0][lr] = va0.x; As[0][lk + 1][lr] = va0.y;
        As[0][lk + 2][lr] = va0.z; As[0][lk + 3][lr] = va0.w;
        As[0][lk + 0][lr + 64] = va1.x; As[0][lk + 1][lr + 64] = va1.y;
        As[0][lk + 2][lr + 64] = va1.z; As[0][lk + 3][lr + 64] = va1.w;
        Bs[0][lk + 0][lr] = vw0.x; Bs[0][lk + 1][lr] = vw0.y;
        Bs[0][lk + 2][lr] = vw0.z; Bs[0][lk + 3][lr] = vw0.w;
        Bs[0][lk + 0][lr + 64] = vw1.x; Bs[0][lk + 1][lr + 64] = vw1.y;
        Bs[0][lk + 2][lr + 64] = vw1.z; Bs[0][lk + 3][lr + 64] = vw1.w;
    }
    __syncthreads();

    int cur = 0;
    for (int kt = 0; kt < K; kt += 16) {
        // prefetch next tile into registers (overlaps with compute)
        float4 va0, va1, vw0, vw1;
        const bool more = (kt + 16 < K);
        if (more) {
            va0 = *(const float4*)(pa0 + kt + 16);
            va1 = *(const float4*)(pa1 + kt + 16);
            vw0 = *(const float4*)(pw0 + kt + 16);
            vw1 = *(const float4*)(pw1 + kt + 16);
        }

#pragma unroll
        for (int k = 0; k < 16; k++) {
            float a[8];
            *(float4*)&a[0] = *(float4*)&As[cur][k][ty * 8];
            *(float4*)&a[4] = *(float4*)&As[cur][k][ty * 8 + 4];
            F4U bl, bh;
            bl.v = *(float4*)&Bs[cur][k][tx * 4];
            bh.v = *(float4*)&Bs[cur][k][tx * 4 + 64];
            unsigned long long bp0 = bl.u[0], bp1 = bl.u[1];
            unsigned long long bp2 = bh.u[0], bp3 = bh.u[1];
#pragma unroll
            for (int i = 0; i < 8; i++) {
                unsigned long long ad = dup2(a[i]);
                ffma2(acc2[i][0], ad, bp0);
                ffma2(acc2[i][1], ad, bp1);
                ffma2(acc2[i][2], ad, bp2);
                ffma2(acc2[i][3], ad, bp3);
            }
        }

        if (more) {
            int nxt = cur ^ 1;
            As[nxt][lk + 0][lr] = va0.x; As[nxt][lk + 1][lr] = va0.y;
            As[nxt][lk + 2][lr] = va0.z; As[nxt][lk + 3][lr] = va0.w;
            As[nxt][lk + 0][lr + 64] = va1.x; As[nxt][lk + 1][lr + 64] = va1.y;
            As[nxt][lk + 2][lr + 64] = va1.z; As[nxt][lk + 3][lr + 64] = va1.w;
            Bs[nxt][lk + 0][lr] = vw0.x; Bs[nxt][lk + 1][lr] = vw0.y;
            Bs[nxt][lk + 2][lr] = vw0.z; Bs[nxt][lk + 3][lr] = vw0.w;
            Bs[nxt][lk + 0][lr + 64] = vw1.x; Bs[nxt][lk + 1][lr + 64] = vw1.y;
            Bs[nxt][lk + 2][lr + 64] = vw1.z; Bs[nxt][lk + 3][lr + 64] = vw1.w;
            __syncthreads();
            cur = nxt;
        }
    }

#pragma unroll
    for (int i = 0; i < 8; i++) {
        int m = m0 + ty * 8 + i;
#pragma unroll
        for (int jg = 0; jg < 2; jg++) {
            int n = n0 + tx * 4 + jg * 64;
            F4U r;
            r.u[0] = acc2[i][jg * 2 + 0];
            r.u[1] = acc2[i][jg * 2 + 1];
            float4 o;
            o.x = r.f[0] + bias[n + 0];
            o.y = r.f[1] + bias[n + 1];
            o.z = r.f[2] + bias[n + 2];
            o.w = r.f[3] + bias[n + 3];
            *(float4*)&g_down_f[(size_t)m * C_OUT + n] = o;
        }
    }
}

// ---------------------------------------------------------------------------
// KNN: per up point, find 3 nearest down points. Rank by t = d2 - 2*dot
// (ordering-equivalent: u2 constant per query). Strict-< insertion keeps
// earliest index on ties (matches top_k stability).
// ---------------------------------------------------------------------------
__global__ __launch_bounds__(256) void knn_kernel(
    const float* __restrict__ up_points,    // [BATCH, N_UP, 3]
    const float* __restrict__ down_points)  // [BATCH, N_DOWN, 3]
{
    __shared__ float4 sp[2048];   // 32 KB: (x, y, z, x^2+y^2+z^2)

    const int b = blockIdx.y;
    const int n = blockIdx.x * 256 + threadIdx.x;

    const float* up = up_points + (size_t)(b * N_UP + n) * 3;
    const float ux = up[0], uy = up[1], uz = up[2];
    const float u2 = ux * ux + uy * uy + uz * uz;
    const float a0 = -2.0f * ux, a1 = -2.0f * uy, a2 = -2.0f * uz;

    float bd0 = CUDART_INF_F, bd1 = CUDART_INF_F, bd2 = CUDART_INF_F;
    int   bi0 = 0, bi1 = 0, bi2 = 0;

    for (int phase = 0; phase < 2; phase++) {
        const int mbase = phase * 2048;
        __syncthreads();
        for (int i = threadIdx.x; i < 2048; i += 256) {
            const float* dp = down_points + (size_t)(b * N_DOWN + mbase + i) * 3;
            float x = dp[0], y = dp[1], z = dp[2];
            sp[i] = make_float4(x, y, z, x * x + y * y + z * z);
        }
        __syncthreads();

        for (int m = 0; m < 2048; m += 8) {
            float t[8];
#pragma unroll
            for (int j = 0; j < 8; j++) {
                float4 p = sp[m + j];
                t[j] = fmaf(a0, p.x, fmaf(a1, p.y, fmaf(a2, p.z, p.w)));
            }
            float mn01 = fminf(t[0], t[1]);
            float mn23 = fminf(t[2], t[3]);
            float mn45 = fminf(t[4], t[5]);
            float mn67 = fminf(t[6], t[7]);
            float mn = fminf(fminf(mn01, mn23), fminf(mn45, mn67));
            if (mn < bd2) {
#pragma unroll
                for (int j = 0; j < 8; j++) {
                    float d = t[j];
                    if (d < bd2) {
                        int mi = mbase + m + j;
                        if (d < bd1) {
                            bd2 = bd1; bi2 = bi1;
                            if (d < bd0) { bd1 = bd0; bi1 = bi0; bd0 = d; bi0 = mi; }
                            else          { bd1 = d;  bi1 = mi; }
                        } else {
                            bd2 = d; bi2 = mi;
                        }
                    }
                }
            }
        }
    }

    float d0 = bd0 + u2, d1 = bd1 + u2, d2 = bd2 + u2;
    float w0 = 1.0f / (d0 + EPSW);
    float w1 = 1.0f / (d1 + EPSW);
    float w2 = 1.0f / (d2 + EPSW);
    float inv = 1.0f / (w0 + w1 + w2);

    const int base = (b * N_UP + n) * KNN;
    g_idx[base + 0] = bi0; g_idx[base + 1] = bi1; g_idx[base + 2] = bi2;
    g_w[base + 0] = w0 * inv; g_w[base + 1] = w1 * inv; g_w[base + 2] = w2 * inv;
}

// ---------------------------------------------------------------------------
// Fused output GEMM + interpolation epilogue:
// out[m, o] = sum_c up_features[m, c]*W_up[o, c] + b_up[o]
//             + sum_k w[m, k] * g_down_f[b, idx[m, k], o]
// M = 65536, N = 512, K = 384
// ---------------------------------------------------------------------------
__global__ __launch_bounds__(256) void fused_out_kernel(
    const float* __restrict__ A,     // up_features [M, C_UP]
    const float* __restrict__ W,     // W_up [C_OUT, C_UP]
    const float* __restrict__ bias,  // b_up [C_OUT]
    float* __restrict__ out)         // [M, C_OUT]
{
    const int K = C_UP;
    __shared__ float As[2][16][128];
    __shared__ float Bs[2][16][128];

    const int tid = threadIdx.x;
    const int m0 = blockIdx.y * 128;
    const int n0 = blockIdx.x * 128;
    const int lr = tid >> 2;
    const int lk = (tid & 3) * 4;
    const int ty = tid >> 4;
    const int tx = tid & 15;

    unsigned long long acc2[8][4];
#pragma unroll
    for (int i = 0; i < 8; i++)
#pragma unroll
        for (int j = 0; j < 4; j++) acc2[i][j] = 0ull;

    const float* pa0 = &A[(size_t)(m0 + lr) * K + lk];
    const float* pa1 = &A[(size_t)(m0 + lr + 64) * K + lk];
    const float* pw0 = &W[(size_t)(n0 + lr) * K + lk];
    const float* pw1 = &W[(size_t)(n0 + lr + 64) * K + lk];

    {
        float4 va0 = *(const float4*)pa0;
        float4 va1 = *(const float4*)pa1;
        float4 vw0 = *(const float4*)pw0;
        float4 vw1 = *(const float4*)pw1;
        As[0][lk + 0][lr] = va0.x; As[0][lk + 1][lr] = va0.y;
        As[0][lk + 2][lr] = va0.z; As[0][lk + 3][lr] = va0.w;
        As[0][lk + 0][lr + 64] = va1.x; As[0][lk + 1][lr + 64] = va1.y;
        As[0][lk + 2][lr + 64] = va1.z; As[0][lk + 3][lr + 64] = va1.w;
        Bs[0][lk + 0][lr] = vw0.x; Bs[0][lk + 1][lr] = vw0.y;
        Bs[0][lk + 2][lr] = vw0.z; Bs[0][lk + 3][lr] = vw0.w;
        Bs[0][lk + 0][lr + 64] = vw1.x; Bs[0][lk + 1][lr + 64] = vw1.y;
        Bs[0][lk + 2][lr + 64] = vw1.z; Bs[0][lk + 3][lr + 64] = vw1.w;
    }
    __syncthreads();

    int cur = 0;
    for (int kt = 0; kt < K; kt += 16) {
        float4 va0, va1, vw0, vw1;
        const bool more = (kt + 16 < K);
        if (more) {
            va0 = *(const float4*)(pa0 + kt + 16);
            va1 = *(const float4*)(pa1 + kt + 16);
            vw0 = *(const float4*)(pw0 + kt + 16);
            vw1 = *(const float4*)(pw1 + kt + 16);
        }

#pragma unroll
        for (int k = 0; k < 16; k++) {
            float a[8];
            *(float4*)&a[0] = *(float4*)&As[cur][k][ty * 8];
            *(float4*)&a[4] = *(float4*)&As[cur][k][ty * 8 + 4];
            F4U bl, bh;
            bl.v = *(float4*)&Bs[cur][k][tx * 4];
            bh.v = *(float4*)&Bs[cur][k][tx * 4 + 64];
            unsigned long long bp0 = bl.u[0], bp1 = bl.u[1];
            unsigned long long bp2 = bh.u[0], bp3 = bh.u[1];
#pragma unroll
            for (int i = 0; i < 8; i++) {
                unsigned long long ad = dup2(a[i]);
                ffma2(acc2[i][0], ad, bp0);
                ffma2(acc2[i][1], ad, bp1);
                ffma2(acc2[i][2], ad, bp2);
                ffma2(acc2[i][3], ad, bp3);
            }
        }

        if (more) {
            int nxt = cur ^ 1;
            As[nxt][lk + 0][lr] = va0.x; As[nxt][lk + 1][lr] = va0.y;
            As[nxt][lk + 2][lr] = va0.z; As[nxt][lk + 3][lr] = va0.w;
            As[nxt][lk + 0][lr + 64] = va1.x; As[nxt][lk + 1][lr + 64] = va1.y;
            As[nxt][lk + 2][lr + 64] = va1.z; As[nxt][lk + 3][lr + 64] = va1.w;
            Bs[nxt][lk + 0][lr] = vw0.x; Bs[nxt][lk + 1][lr] = vw0.y;
            Bs[nxt][lk + 2][lr] = vw0.z; Bs[nxt][lk + 3][lr] = vw0.w;
            Bs[nxt][lk + 0][lr + 64] = vw1.x; Bs[nxt][lk + 1][lr + 64] = vw1.y;
            Bs[nxt][lk + 2][lr + 64] = vw1.z; Bs[nxt][lk + 3][lr + 64] = vw1.w;
            __syncthreads();
            cur = nxt;
        }
    }

#pragma unroll
    for (int i = 0; i < 8; i++) {
        const int m = m0 + ty * 8 + i;
        const int bb = m >> 14;   // m / N_UP
        const float* df = g_down_f + (size_t)bb * N_DOWN * C_OUT;
        const int ib = m * KNN;
        const int i0 = g_idx[ib + 0], i1 = g_idx[ib + 1], i2 = g_idx[ib + 2];
        const float w0 = g_w[ib + 0], w1 = g_w[ib + 1], w2 = g_w[ib + 2];
#pragma unroll
        for (int jg = 0; jg < 2; jg++) {
            const int n = n0 + tx * 4 + jg * 64;
            float4 f0 = *(const float4*)&df[(size_t)i0 * C_OUT + n];
            float4 f1 = *(const float4*)&df[(size_t)i1 * C_OUT + n];
            float4 f2 = *(const float4*)&df[(size_t)i2 * C_OUT + n];
            F4U r;
            r.u[0] = acc2[i][jg * 2 + 0];
            r.u[1] = acc2[i][jg * 2 + 1];
            float4 o;
            o.x = r.f[0] + bias[n + 0] + w0 * f0.x + w1 * f1.x + w2 * f2.x;
            o.y = r.f[1] + bias[n + 1] + w0 * f0.y + w1 * f1.y + w2 * f2.y;
            o.z = r.f[2] + bias[n + 2] + w0 * f0.z + w1 * f1.z + w2 * f2.z;
            o.w = r.f[3] + bias[n + 3] + w0 * f0.w + w1 * f1.w + w2 * f2.w;
            *(float4*)&out[(size_t)m * C_OUT + n] = o;
        }
    }
}

// ---------------------------------------------------------------------------
extern "C" void kernel_launch(void* const* d_in, const int* in_sizes, int n_in,
                              void* d_out, int out_size) {
    (void)in_sizes; (void)n_in; (void)out_size;
    const float* up_points     = (const float*)d_in[0];
    const float* up_features   = (const float*)d_in[1];
    const float* down_points   = (const float*)d_in[2];
    const float* down_features = (const float*)d_in[3];
    const float* W_up          = (const float*)d_in[4];
    const float* b_up          = (const float*)d_in[5];
    const float* W_down        = (const float*)d_in[6];
    const float* b_down        = (const float*)d_in[7];
    float* out = (float*)d_out;

    dim3 g1(C_OUT / 128, (BATCH * N_DOWN) / 128);   // (4, 128)
    gemm_down_kernel<<<g1, 256>>>(down_features, W_down, b_down);

    dim3 g2(N_UP / 256, BATCH);                      // (64, 4)
    knn_kernel<<<g2, 256>>>(up_points, down_points);

    dim3 g3(C_OUT / 128, (BATCH * N_UP) / 128);      // (4, 512)
    fused_out_kernel<<<g3, 256>>>(up_features, W_up, b_up, out);
}

// round 4
// speedup vs baseline: 1.5096x; 1.4031x over previous
#include <cuda_runtime.h>
#include <math_constants.h>
#include <cstdint>

#define BATCH   4
#define N_UP    16384
#define N_DOWN  4096
#define C_UP    384
#define C_DOWN  512
#define C_OUT   512
#define KNN     3
#define EPSW    1e-8f

#define M_UP   (BATCH * N_UP)     // 65536
#define M_DN   (BATCH * N_DOWN)   // 16384

// ---------------- scratch (__device__ globals; no allocs allowed) ----------
__device__ float g_down_f[M_DN * C_OUT];                 // 32 MB fp32
__device__ int   g_idx[M_UP * KNN];
__device__ float g_w[M_UP * KNN];

__device__ unsigned short g_Ah_up[(size_t)M_UP * C_UP];  // bf16 hi of up_features
__device__ unsigned short g_Al_up[(size_t)M_UP * C_UP];  // bf16 lo
__device__ unsigned short g_Wh_up[(size_t)C_OUT * C_UP];
__device__ unsigned short g_Wl_up[(size_t)C_OUT * C_UP];
__device__ unsigned short g_Ah_dn[(size_t)M_DN * C_DOWN];
__device__ unsigned short g_Al_dn[(size_t)M_DN * C_DOWN];
__device__ unsigned short g_Wh_dn[(size_t)C_OUT * C_DOWN];
__device__ unsigned short g_Wl_dn[(size_t)C_OUT * C_DOWN];

// ---------------- helpers ---------------------------------------------------
static __device__ __forceinline__ uint32_t smem_u32(const void* p) {
    uint32_t a;
    asm("{ .reg .u64 t; cvta.to.shared.u64 t, %1; cvt.u32.u64 %0, t; }"
        : "=r"(a) : "l"(p));
    return a;
}
static __device__ __forceinline__ unsigned short f2bf(float f) {
    unsigned short u;
    asm("cvt.rn.bf16.f32 %0, %1;" : "=h"(u) : "f"(f));
    return u;
}
static __device__ __forceinline__ float bf2f(unsigned short u) {
    return __uint_as_float(((uint32_t)u) << 16);
}
static __device__ __forceinline__ void cp16(uint32_t dst, const void* src) {
    asm volatile("cp.async.cg.shared.global [%0], [%1], 16;"
                 :: "r"(dst), "l"(src) : "memory");
}
static __device__ __forceinline__ void cp_commit() {
    asm volatile("cp.async.commit_group;" ::: "memory");
}
static __device__ __forceinline__ void cp_wait1() {
    asm volatile("cp.async.wait_group 1;" ::: "memory");
}
static __device__ __forceinline__ void ldmx4(uint32_t& r0, uint32_t& r1,
                                             uint32_t& r2, uint32_t& r3,
                                             uint32_t addr) {
    asm volatile("ldmatrix.sync.aligned.m8n8.x4.shared.b16 {%0,%1,%2,%3}, [%4];"
                 : "=r"(r0), "=r"(r1), "=r"(r2), "=r"(r3) : "r"(addr));
}
static __device__ __forceinline__ void mma16816(float* c, const uint32_t* a,
                                                uint32_t b0, uint32_t b1) {
    asm volatile(
        "mma.sync.aligned.m16n8k16.row.col.f32.bf16.bf16.f32 "
        "{%0,%1,%2,%3}, {%4,%5,%6,%7}, {%8,%9}, {%0,%1,%2,%3};"
        : "+f"(c[0]), "+f"(c[1]), "+f"(c[2]), "+f"(c[3])
        : "r"(a[0]), "r"(a[1]), "r"(a[2]), "r"(a[3]), "r"(b0), "r"(b1));
}

// ---------------- hi/lo bf16 split -----------------------------------------
__global__ __launch_bounds__(256) void conv_hilo(
    const float4* __restrict__ x, ushort4* __restrict__ h4,
    ushort4* __restrict__ l4, int n4)
{
    int i = blockIdx.x * 256 + threadIdx.x;
    if (i >= n4) return;
    float4 v = x[i];
    ushort4 h, l;
    h.x = f2bf(v.x); l.x = f2bf(v.x - bf2f(h.x));
    h.y = f2bf(v.y); l.y = f2bf(v.y - bf2f(h.y));
    h.z = f2bf(v.z); l.z = f2bf(v.z - bf2f(h.z));
    h.w = f2bf(v.w); l.w = f2bf(v.w - bf2f(h.w));
    h4[i] = h; l4[i] = l;
}

// ---------------------------------------------------------------------------
// bf16 hi/lo GEMM via mma.sync: out[m,n] = sum_k A[m,k]*Wt[n,k] + bias[n]
// (+ KNN interpolation when FUSED). Effective K' = 3K via segments:
//   seg0: Ah*Bh   seg1: Ah*Bl   seg2: Al*Bh
// CTA 128x128, BK=32 bf16, 2-stage cp.async pipeline, 8 warps (2x4),
// warp tile 64x32, m16n8k16.
// ---------------------------------------------------------------------------
template<int K, bool FUSED>
__global__ __launch_bounds__(256) void gemm_bf16(
    const unsigned short* __restrict__ Ah, const unsigned short* __restrict__ Al,
    const unsigned short* __restrict__ Bh, const unsigned short* __restrict__ Bl,
    const float* __restrict__ bias, float* __restrict__ outp)
{
    constexpr int SEGC = K / 32;
    constexpr int NC = 3 * SEGC;
    // 128 rows x 80B (64B data + 16B pad for conflict-free ldmatrix), A+B, x2
    __shared__ __align__(16) unsigned short smt[20480];
    const uint32_t sbase = smem_u32(smt);

    const int tid = threadIdx.x;
    const int lane = tid & 31;
    const int wid = tid >> 5;
    const int wm = wid >> 2;        // 0..1 -> m offset wm*64
    const int wn = wid & 3;         // 0..3 -> n offset wn*32
    const int m0 = blockIdx.y * 128;
    const int n0 = blockIdx.x * 128;

    // cp.async slots: thread covers rows (row, row+64), 16B chunk q
    const int row = tid >> 2;
    const int q = tid & 3;

    // ldmatrix per-lane offsets
    const int lq = lane >> 3, l7 = lane & 7;
    const int aRow = (lq & 1) * 8 + l7, aK = (lq >> 1) * 8;
    const int bRow = (lq >> 1) * 8 + l7, bK = (lq & 1) * 8;

    float acc[4][4][4];
#pragma unroll
    for (int i = 0; i < 4; i++)
#pragma unroll
        for (int j = 0; j < 4; j++)
#pragma unroll
            for (int r = 0; r < 4; r++) acc[i][j][r] = 0.0f;

    auto issue = [&](int c, int s) {
        const int seg = c / SEGC;
        const int kk = (c - seg * SEGC) * 32;
        const unsigned short* As = (seg < 2) ? Ah : Al;
        const unsigned short* Bs = (seg == 1) ? Bl : Bh;
        const unsigned short* srcA = As + (size_t)(m0 + row) * K + kk + q * 8;
        const unsigned short* srcB = Bs + (size_t)(n0 + row) * K + kk + q * 8;
        uint32_t dA = sbase + s * 20480 + row * 80 + q * 16;
        uint32_t dB = dA + 10240;
        cp16(dA, srcA);
        cp16(dA + 64 * 80, srcA + (size_t)64 * K);
        cp16(dB, srcB);
        cp16(dB + 64 * 80, srcB + (size_t)64 * K);
    };

    issue(0, 0);
    cp_commit();

    for (int c = 0; c < NC; c++) {
        const int s = c & 1;
        if (c + 1 < NC) issue(c + 1, s ^ 1);
        cp_commit();
        cp_wait1();
        __syncthreads();

        const uint32_t sa = sbase + s * 20480;
        const uint32_t sb = sa + 10240;
#pragma unroll
        for (int ks = 0; ks < 2; ks++) {
            uint32_t a[4][4];
#pragma unroll
            for (int i = 0; i < 4; i++) {
                uint32_t addr = sa + (uint32_t)(wm * 64 + i * 16 + aRow) * 80
                              + (uint32_t)(ks * 16 + aK) * 2;
                ldmx4(a[i][0], a[i][1], a[i][2], a[i][3], addr);
            }
            uint32_t b[4][2];
#pragma unroll
            for (int jp = 0; jp < 2; jp++) {
                uint32_t addr = sb + (uint32_t)(wn * 32 + jp * 16 + bRow) * 80
                              + (uint32_t)(ks * 16 + bK) * 2;
                ldmx4(b[jp * 2][0], b[jp * 2][1], b[jp * 2 + 1][0], b[jp * 2 + 1][1], addr);
            }
#pragma unroll
            for (int i = 0; i < 4; i++)
#pragma unroll
                for (int j = 0; j < 4; j++)
                    mma16816(acc[i][j], a[i], b[j][0], b[j][1]);
        }
        __syncthreads();
    }

    // ---------------- epilogue ----------------
    float* obase = FUSED ? outp : g_down_f;
#pragma unroll
    for (int i = 0; i < 4; i++) {
        const int r0 = m0 + wm * 64 + i * 16 + (lane >> 2);
        const int r1 = r0 + 8;
        const float* df0 = nullptr; const float* df1 = nullptr;
        int i00=0,i01=0,i02=0, i10=0,i11=0,i12=0;
        float w00=0,w01=0,w02=0, w10=0,w11=0,w12=0;
        if (FUSED) {
            const float* dfb0 = g_down_f + (size_t)(r0 >> 14) * N_DOWN * C_OUT;
            const float* dfb1 = g_down_f + (size_t)(r1 >> 14) * N_DOWN * C_OUT;
            df0 = dfb0; df1 = dfb1;
            int ib0 = r0 * KNN, ib1 = r1 * KNN;
            i00 = g_idx[ib0]; i01 = g_idx[ib0+1]; i02 = g_idx[ib0+2];
            w00 = g_w[ib0];   w01 = g_w[ib0+1];   w02 = g_w[ib0+2];
            i10 = g_idx[ib1]; i11 = g_idx[ib1+1]; i12 = g_idx[ib1+2];
            w10 = g_w[ib1];   w11 = g_w[ib1+1];   w12 = g_w[ib1+2];
        }
#pragma unroll
        for (int j = 0; j < 4; j++) {
            const int n = n0 + wn * 32 + j * 8 + (lane & 3) * 2;
            const float2 bi = *(const float2*)(bias + n);
            float2 o0, o1;
            o0.x = acc[i][j][0] + bi.x;  o0.y = acc[i][j][1] + bi.y;
            o1.x = acc[i][j][2] + bi.x;  o1.y = acc[i][j][3] + bi.y;
            if (FUSED) {
                float2 a0 = *(const float2*)(df0 + (size_t)i00 * C_OUT + n);
                float2 a1 = *(const float2*)(df0 + (size_t)i01 * C_OUT + n);
                float2 a2 = *(const float2*)(df0 + (size_t)i02 * C_OUT + n);
                o0.x += w00 * a0.x + w01 * a1.x + w02 * a2.x;
                o0.y += w00 * a0.y + w01 * a1.y + w02 * a2.y;
                float2 c0 = *(const float2*)(df1 + (size_t)i10 * C_OUT + n);
                float2 c1 = *(const float2*)(df1 + (size_t)i11 * C_OUT + n);
                float2 c2 = *(const float2*)(df1 + (size_t)i12 * C_OUT + n);
                o1.x += w10 * c0.x + w11 * c1.x + w12 * c2.x;
                o1.y += w10 * c0.y + w11 * c1.y + w12 * c2.y;
            }
            *(float2*)(obase + (size_t)r0 * C_OUT + n) = o0;
            *(float2*)(obase + (size_t)r1 * C_OUT + n) = o1;
        }
    }
}

// ---------------------------------------------------------------------------
// KNN (unchanged): rank by t = d2 - 2*dot; strict-< insertion for stability.
// ---------------------------------------------------------------------------
__global__ __launch_bounds__(256) void knn_kernel(
    const float* __restrict__ up_points,
    const float* __restrict__ down_points)
{
    __shared__ float4 sp[2048];

    const int b = blockIdx.y;
    const int n = blockIdx.x * 256 + threadIdx.x;

    const float* up = up_points + (size_t)(b * N_UP + n) * 3;
    const float ux = up[0], uy = up[1], uz = up[2];
    const float u2 = ux * ux + uy * uy + uz * uz;
    const float a0 = -2.0f * ux, a1 = -2.0f * uy, a2 = -2.0f * uz;

    float bd0 = CUDART_INF_F, bd1 = CUDART_INF_F, bd2 = CUDART_INF_F;
    int   bi0 = 0, bi1 = 0, bi2 = 0;

    for (int phase = 0; phase < 2; phase++) {
        const int mbase = phase * 2048;
        __syncthreads();
        for (int i = threadIdx.x; i < 2048; i += 256) {
            const float* dp = down_points + (size_t)(b * N_DOWN + mbase + i) * 3;
            float x = dp[0], y = dp[1], z = dp[2];
            sp[i] = make_float4(x, y, z, x * x + y * y + z * z);
        }
        __syncthreads();

        for (int m = 0; m < 2048; m += 8) {
            float t[8];
#pragma unroll
            for (int j = 0; j < 8; j++) {
                float4 p = sp[m + j];
                t[j] = fmaf(a0, p.x, fmaf(a1, p.y, fmaf(a2, p.z, p.w)));
            }
            float mn = fminf(fminf(fminf(t[0], t[1]), fminf(t[2], t[3])),
                             fminf(fminf(t[4], t[5]), fminf(t[6], t[7])));
            if (mn < bd2) {
#pragma unroll
                for (int j = 0; j < 8; j++) {
                    float d = t[j];
                    if (d < bd2) {
                        int mi = mbase + m + j;
                        if (d < bd1) {
                            bd2 = bd1; bi2 = bi1;
                            if (d < bd0) { bd1 = bd0; bi1 = bi0; bd0 = d; bi0 = mi; }
                            else          { bd1 = d;  bi1 = mi; }
                        } else {
                            bd2 = d; bi2 = mi;
                        }
                    }
                }
            }
        }
    }

    float d0 = bd0 + u2, d1 = bd1 + u2, d2 = bd2 + u2;
    float w0 = 1.0f / (d0 + EPSW);
    float w1 = 1.0f / (d1 + EPSW);
    float w2 = 1.0f / (d2 + EPSW);
    float inv = 1.0f / (w0 + w1 + w2);

    const int base = (b * N_UP + n) * KNN;
    g_idx[base + 0] = bi0; g_idx[base + 1] = bi1; g_idx[base + 2] = bi2;
    g_w[base + 0] = w0 * inv; g_w[base + 1] = w1 * inv; g_w[base + 2] = w2 * inv;
}

// ---------------------------------------------------------------------------
extern "C" void kernel_launch(void* const* d_in, const int* in_sizes, int n_in,
                              void* d_out, int out_size) {
    (void)in_sizes; (void)n_in; (void)out_size;
    const float* up_points     = (const float*)d_in[0];
    const float* up_features   = (const float*)d_in[1];
    const float* down_points   = (const float*)d_in[2];
    const float* down_features = (const float*)d_in[3];
    const float* W_up          = (const float*)d_in[4];
    const float* b_up          = (const float*)d_in[5];
    const float* W_down        = (const float*)d_in[6];
    const float* b_down        = (const float*)d_in[7];
    float* out = (float*)d_out;

    void *pAhU, *pAlU, *pWhU, *pWlU, *pAhD, *pAlD, *pWhD, *pWlD;
    cudaGetSymbolAddress(&pAhU, g_Ah_up);
    cudaGetSymbolAddress(&pAlU, g_Al_up);
    cudaGetSymbolAddress(&pWhU, g_Wh_up);
    cudaGetSymbolAddress(&pWlU, g_Wl_up);
    cudaGetSymbolAddress(&pAhD, g_Ah_dn);
    cudaGetSymbolAddress(&pAlD, g_Al_dn);
    cudaGetSymbolAddress(&pWhD, g_Wh_dn);
    cudaGetSymbolAddress(&pWlD, g_Wl_dn);

    // hi/lo splits
    {
        int n4 = M_UP * C_UP / 4;
        conv_hilo<<<(n4 + 255) / 256, 256>>>((const float4*)up_features,
                                             (ushort4*)pAhU, (ushort4*)pAlU, n4);
    }
    {
        int n4 = C_OUT * C_UP / 4;
        conv_hilo<<<(n4 + 255) / 256, 256>>>((const float4*)W_up,
                                             (ushort4*)pWhU, (ushort4*)pWlU, n4);
    }
    {
        int n4 = M_DN * C_DOWN / 4;
        conv_hilo<<<(n4 + 255) / 256, 256>>>((const float4*)down_features,
                                             (ushort4*)pAhD, (ushort4*)pAlD, n4);
    }
    {
        int n4 = C_OUT * C_DOWN / 4;
        conv_hilo<<<(n4 + 255) / 256, 256>>>((const float4*)W_down,
                                             (ushort4*)pWhD, (ushort4*)pWlD, n4);
    }

    dim3 gk(N_UP / 256, BATCH);
    knn_kernel<<<gk, 256>>>(up_points, down_points);

    dim3 g1(C_OUT / 128, M_DN / 128);   // (4, 128)
    gemm_bf16<C_DOWN, false><<<g1, 256>>>(
        (const unsigned short*)pAhD, (const unsigned short*)pAlD,
        (const unsigned short*)pWhD, (const unsigned short*)pWlD,
        b_down, nullptr);

    dim3 g2(C_OUT / 128, M_UP / 128);   // (4, 512)
    gemm_bf16<C_UP, true><<<g2, 256>>>(
        (const unsigned short*)pAhU, (const unsigned short*)pAlU,
        (const unsigned short*)pWhU, (const unsigned short*)pWlU,
        b_up, out);
}